// round 1
// baseline (speedup 1.0000x reference)
#include <cuda_runtime.h>
#include <math_constants.h>

// Problem constants
#define Bb 8
#define Ll 256
#define Aa 15
#define Kk 9
#define TB 16

// Output layout (float32, concatenated flattened tuple):
//   [0, 30720)              block_id  = i / A
//   [30720, 32768)          batch_id  = i / L
//   [32768, 106496)         edges [2, 36864] row-major
//                             row0 = src (intra 18432 | inter 18432)
//                             row1 = dst (intra 18432 | inter 18432)
//   [106496, 696320)        edge_attr [36864, 16]
#define OFF_BATCH   30720
#define OFF_EDGES   32768
#define OFF_ATTR    106496
#define N_OUT       696320
#define EDGES_HALF  18432   // B*L*K
#define EDGES_ROW   36864   // 2*B*L*K

// Scratch: min squared distance between blocks, [B, L, L]
__device__ float g_d2min[Bb * Ll * Ll];

// ---------------------------------------------------------------------------
// Kernel 1: block-pair min squared distance.
// One CTA computes a 16x16 tile of block pairs for one batch.
// d2 = |xi|^2 + |xj|^2 - 2*<xi,xj>, computed with explicit RN mul/add to
// match JAX's non-contracted fp32 arithmetic (ranking-stable vs reference).
// ---------------------------------------------------------------------------
__global__ void __launch_bounds__(256) block_dist_kernel(const float* __restrict__ pos) {
    __shared__ float sIx[TB * Aa], sIy[TB * Aa], sIz[TB * Aa], sIn[TB * Aa];
    __shared__ float sJx[TB * Aa], sJy[TB * Aa], sJz[TB * Aa], sJn[TB * Aa];

    const int b  = blockIdx.z;
    const int i0 = blockIdx.y * TB;
    const int j0 = blockIdx.x * TB;
    const int t  = threadIdx.x;

    if (t < TB * Aa) {
        const int blk = t / Aa;
        const int at  = t % Aa;
        {
            const float* p = pos + ((size_t)((b * Ll + i0 + blk) * Aa + at)) * 3;
            float x = p[0], y = p[1], z = p[2];
            sIx[t] = x; sIy[t] = y; sIz[t] = z;
            sIn[t] = __fadd_rn(__fadd_rn(__fmul_rn(x, x), __fmul_rn(y, y)), __fmul_rn(z, z));
        }
        {
            const float* p = pos + ((size_t)((b * Ll + j0 + blk) * Aa + at)) * 3;
            float x = p[0], y = p[1], z = p[2];
            sJx[t] = x; sJy[t] = y; sJz[t] = z;
            sJn[t] = __fadd_rn(__fadd_rn(__fmul_rn(x, x), __fmul_rn(y, y)), __fmul_rn(z, z));
        }
    }
    __syncthreads();

    const int ii = t >> 4;
    const int jj = t & 15;

    // J-side atoms register-resident
    float jx[Aa], jy[Aa], jz[Aa], jn[Aa];
#pragma unroll
    for (int a = 0; a < Aa; a++) {
        const int s = jj * Aa + a;
        jx[a] = sJx[s]; jy[a] = sJy[s]; jz[a] = sJz[s]; jn[a] = sJn[s];
    }

    float m = CUDART_INF_F;
    for (int a = 0; a < Aa; a++) {   // I-side streamed (not unrolled: keep I$ small)
        const int s = ii * Aa + a;
        const float x = sIx[s], y = sIy[s], z = sIz[s], n = sIn[s];
#pragma unroll
        for (int c = 0; c < Aa; c++) {
            float dot = __fadd_rn(__fadd_rn(__fmul_rn(x, jx[c]), __fmul_rn(y, jy[c])),
                                  __fmul_rn(z, jz[c]));
            float d2  = __fadd_rn(__fadd_rn(n, jn[c]), __fmul_rn(-2.0f, dot));
            d2 = fmaxf(d2, 0.0f);
            m = fminf(m, d2);
        }
    }
    g_d2min[(size_t)b * Ll * Ll + (size_t)(i0 + ii) * Ll + (j0 + jj)] = m;
}

// ---------------------------------------------------------------------------
// Kernel 2: KNN (K=9) per (type, b, l). One warp per row.
// Each lane owns 8 candidates; 9 rounds of warp argmin with tie-break on
// smallest global index (matches jax.lax.top_k stability on -dm).
// ---------------------------------------------------------------------------
__global__ void __launch_bounds__(256) knn_kernel(const int* __restrict__ frag,
                                                  float* __restrict__ out) {
    const int gwarp = (blockIdx.x * blockDim.x + threadIdx.x) >> 5;
    const int lane  = threadIdx.x & 31;
    if (gwarp >= 2 * Bb * Ll) return;

    const int type = gwarp / (Bb * Ll);          // 0 = intra, 1 = inter
    const int rem  = gwarp % (Bb * Ll);
    const int b    = rem / Ll;
    const int l    = rem % Ll;

    const int fi   = frag[b * Ll + l];
    const int segi = (fi == 2) ? 1 : fi;

    const float* drow = g_d2min + (size_t)b * Ll * Ll + (size_t)l * Ll;

    float v[8];
    int   id[8];
#pragma unroll
    for (int u = 0; u < 8; u++) {
        const int j  = lane * 8 + u;
        const int fj = frag[b * Ll + j];
        const int segj = (fj == 2) ? 1 : fj;
        const bool ok = (type == 0) ? (segj == segi && j != l) : (segj != segi);
        v[u]  = ok ? drow[j] : CUDART_INF_F;
        id[u] = j;
    }

    const size_t base = (size_t)OFF_EDGES + EDGES_ROW      // dst row
                      + (size_t)type * EDGES_HALF
                      + (size_t)(b * Ll + l) * Kk;

    for (int k = 0; k < Kk; k++) {
        float bv = CUDART_INF_F;
        int   bi = 0x7fffffff;
#pragma unroll
        for (int u = 0; u < 8; u++) {
            if (v[u] < bv || (v[u] == bv && id[u] < bi)) { bv = v[u]; bi = id[u]; }
        }
#pragma unroll
        for (int off = 16; off > 0; off >>= 1) {
            const float ov = __shfl_xor_sync(0xffffffffu, bv, off);
            const int   oi = __shfl_xor_sync(0xffffffffu, bi, off);
            if (ov < bv || (ov == bv && oi < bi)) { bv = ov; bi = oi; }
        }
        if (lane == 0) out[base + k] = (float)(bi + b * Ll);
#pragma unroll
        for (int u = 0; u < 8; u++) {
            if (id[u] == bi) v[u] = CUDART_INF_F;
        }
    }
}

// ---------------------------------------------------------------------------
// Kernel 3: fill all statically-determined output regions (block_id, batch_id,
// edge src ids, edge_attr). Writes 0 in the dst region (overwritten by knn).
// ---------------------------------------------------------------------------
__global__ void __launch_bounds__(256) fill_kernel(const float* __restrict__ edge_emb,
                                                   float* __restrict__ out) {
    const int i = blockIdx.x * blockDim.x + threadIdx.x;
    if (i >= N_OUT) return;

    float val;
    if (i < OFF_BATCH) {
        val = (float)(i / Aa);                       // block_id
    } else if (i < OFF_EDGES) {
        val = (float)((i - OFF_BATCH) / Ll);         // batch_id
    } else if (i < OFF_ATTR) {
        const int e   = i - OFF_EDGES;
        const int row = e / EDGES_ROW;               // 0 = src, 1 = dst
        const int c   = e % EDGES_ROW;
        const int p   = c % EDGES_HALF;              // position within intra/inter half
        const int b   = p / (Ll * Kk);
        const int l   = (p / Kk) % Ll;
        val = (row == 0) ? (float)(l + b * Ll) : 0.0f;  // dst overwritten later
    } else {
        const int e    = i - OFF_ATTR;
        const int r    = e >> 4;
        const int col  = e & 15;
        const int type = (r >= EDGES_HALF) ? 1 : 0;
        val = edge_emb[type * 16 + col];
    }
    out[i] = val;
}

// ---------------------------------------------------------------------------
extern "C" void kernel_launch(void* const* d_in, const int* in_sizes, int n_in,
                              void* d_out, int out_size) {
    const float* pos      = (const float*)d_in[0];  // [B,L,A,3] f32
    const int*   frag     = (const int*)  d_in[6];  // [B,L] i32
    const float* edge_emb = (const float*)d_in[7];  // [2,16] f32
    float* out = (float*)d_out;

    // 1) block pairwise min distances
    {
        dim3 grid(Ll / TB, Ll / TB, Bb);
        block_dist_kernel<<<grid, 256>>>(pos);
    }
    // 2) static output regions (+ zero the dst region)
    {
        const int n = N_OUT;
        fill_kernel<<<(n + 255) / 256, 256>>>(edge_emb, out);
    }
    // 3) KNN -> dst ids
    {
        const int nwarps = 2 * Bb * Ll;            // 4096 warps
        const int threads = nwarps * 32;
        knn_kernel<<<(threads + 255) / 256, 256>>>(frag, out);
    }
    (void)in_sizes; (void)n_in; (void)out_size;
}

// round 2
// speedup vs baseline: 1.8868x; 1.8868x over previous
#include <cuda_runtime.h>
#include <math_constants.h>

// Problem constants
#define Bb 8
#define Ll 256
#define Aa 15
#define Kk 9
#define TB 16
#define NTILES 136   // 16*17/2 upper-triangular 16x16 tiles

// Output layout (float32, concatenated flattened tuple):
//   [0, 30720)        block_id = i / A
//   [30720, 32768)    batch_id = i / L
//   [32768, 106496)   edges [2, 36864]: row0=src, row1=dst; each (intra|inter)
//   [106496, 696320)  edge_attr [36864, 16]
#define OFF_BATCH   30720
#define OFF_EDGES   32768
#define OFF_ATTR    106496
#define N_OUT       696320
#define EDGES_HALF  18432   // B*L*K
#define EDGES_ROW   36864   // 2*B*L*K

#define KNN_CTAS    512     // 4096 warps (2*B*L), 8 warps/CTA
#define FILL_CTAS   2720    // ceil(N_OUT/256)

// Scratch: rank-equivalent block distance (= d2min/2), [B, L, L]
__device__ float g_d2min[Bb * Ll * Ll];

// ---------------------------------------------------------------------------
// Kernel 1: block-pair min "half squared distance", upper-triangular tiles.
// d2' = hn_i + hn_j - <xi,xj>  (== d2/2, rank-equivalent for per-row top-k).
// hn_j seeds the FMA chain; hn_i hoisted out of inner min; clamp hoisted out
// of both mins (max(.,0) is monotone). 4 issue slots per atom pair.
// Each CTA writes its 16x16 tile to both (i,j) and (j,i).
// ---------------------------------------------------------------------------
__global__ void __launch_bounds__(256) block_dist_kernel(const float* __restrict__ pos) {
    __shared__ float sIx[TB * Aa], sIy[TB * Aa], sIz[TB * Aa], sIn[TB * Aa];
    __shared__ float sJx[TB * Aa], sJy[TB * Aa], sJz[TB * Aa], sJn[TB * Aa];

    const int b = blockIdx.y;

    // triangular tile index -> (ti, tj), ti <= tj
    int r = blockIdx.x, ti = 0;
    while (r >= (TB - ti)) { r -= (TB - ti); ti++; }
    const int tj = ti + r;
    const int i0 = ti * TB, j0 = tj * TB;

    const int t = threadIdx.x;
    if (t < TB * Aa) {
        const int blk = t / Aa;
        const int at  = t % Aa;
        {
            const float* p = pos + ((size_t)((b * Ll + i0 + blk) * Aa + at)) * 3;
            float x = p[0], y = p[1], z = p[2];
            sIx[t] = x; sIy[t] = y; sIz[t] = z;
            sIn[t] = 0.5f * (x * x + y * y + z * z);
        }
        {
            const float* p = pos + ((size_t)((b * Ll + j0 + blk) * Aa + at)) * 3;
            float x = p[0], y = p[1], z = p[2];
            sJx[t] = x; sJy[t] = y; sJz[t] = z;
            sJn[t] = 0.5f * (x * x + y * y + z * z);
        }
    }
    __syncthreads();

    const int ii = t >> 4;
    const int jj = t & 15;

    // J-side atoms register-resident
    float jx[Aa], jy[Aa], jz[Aa], jn[Aa];
#pragma unroll
    for (int a = 0; a < Aa; a++) {
        const int s = jj * Aa + a;
        jx[a] = sJx[s]; jy[a] = sJy[s]; jz[a] = sJz[s]; jn[a] = sJn[s];
    }

    float m = CUDART_INF_F;
    for (int a = 0; a < Aa; a++) {   // I-side streamed from smem
        const int s = ii * Aa + a;
        const float x = sIx[s], y = sIy[s], z = sIz[s], hni = sIn[s];
        float mloc = CUDART_INF_F;
#pragma unroll
        for (int c = 0; c < Aa; c++) {
            float acc = jn[c];
            acc = fmaf(-x, jx[c], acc);
            acc = fmaf(-y, jy[c], acc);
            acc = fmaf(-z, jz[c], acc);
            mloc = fminf(mloc, acc);
        }
        m = fminf(m, mloc + hni);
    }
    m = fmaxf(m, 0.0f);

    float* g = g_d2min + (size_t)b * Ll * Ll;
    g[(size_t)(i0 + ii) * Ll + (j0 + jj)] = m;
    g[(size_t)(j0 + jj) * Ll + (i0 + ii)] = m;
}

// ---------------------------------------------------------------------------
// Kernel 2 (merged): KNN dst ids (CTAs [0,512)) + static fills (rest).
// KNN: one warp per (type,b,l); 8 candidates/lane; K=9 rounds of warp argmin
// with smallest-index tie-break (matches jax.lax.top_k stability).
// ---------------------------------------------------------------------------
__global__ void __launch_bounds__(256) knn_fill_kernel(const int* __restrict__ frag,
                                                       const float* __restrict__ edge_emb,
                                                       float* __restrict__ out) {
    if (blockIdx.x < KNN_CTAS) {
        const int gwarp = (blockIdx.x * blockDim.x + threadIdx.x) >> 5;
        const int lane  = threadIdx.x & 31;

        const int type = gwarp / (Bb * Ll);          // 0 = intra, 1 = inter
        const int rem  = gwarp % (Bb * Ll);
        const int b    = rem / Ll;
        const int l    = rem % Ll;

        const int fi   = frag[b * Ll + l];
        const int segi = (fi == 2) ? 1 : fi;

        const float* drow = g_d2min + (size_t)b * Ll * Ll + (size_t)l * Ll;

        float v[8];
        int   id[8];
#pragma unroll
        for (int u = 0; u < 8; u++) {
            const int j  = lane * 8 + u;
            const int fj = frag[b * Ll + j];
            const int segj = (fj == 2) ? 1 : fj;
            const bool ok = (type == 0) ? (segj == segi && j != l) : (segj != segi);
            v[u]  = ok ? drow[j] : CUDART_INF_F;
            id[u] = j;
        }

        const size_t base = (size_t)OFF_EDGES + EDGES_ROW   // dst row
                          + (size_t)type * EDGES_HALF
                          + (size_t)(b * Ll + l) * Kk;

        for (int k = 0; k < Kk; k++) {
            float bv = CUDART_INF_F;
            int   bi = 0x7fffffff;
#pragma unroll
            for (int u = 0; u < 8; u++) {
                if (v[u] < bv || (v[u] == bv && id[u] < bi)) { bv = v[u]; bi = id[u]; }
            }
#pragma unroll
            for (int off = 16; off > 0; off >>= 1) {
                const float ov = __shfl_xor_sync(0xffffffffu, bv, off);
                const int   oi = __shfl_xor_sync(0xffffffffu, bi, off);
                if (ov < bv || (ov == bv && oi < bi)) { bv = ov; bi = oi; }
            }
            if (lane == 0) out[base + k] = (float)(bi + b * Ll);
#pragma unroll
            for (int u = 0; u < 8; u++) {
                if (id[u] == bi) v[u] = CUDART_INF_F;
            }
        }
    } else {
        const int i = (blockIdx.x - KNN_CTAS) * blockDim.x + threadIdx.x;
        if (i >= N_OUT) return;

        float val;
        if (i < OFF_BATCH) {
            val = (float)(i / Aa);                       // block_id
        } else if (i < OFF_EDGES) {
            val = (float)((i - OFF_BATCH) / Ll);         // batch_id
        } else if (i < OFF_ATTR) {
            const int e   = i - OFF_EDGES;
            const int row = e / EDGES_ROW;               // 0 = src, 1 = dst
            const int c   = e % EDGES_ROW;
            const int p   = c % EDGES_HALF;
            const int b   = p / (Ll * Kk);
            const int l   = (p / Kk) % Ll;
            val = (row == 0) ? (float)(l + b * Ll) : 0.0f;  // dst overwritten by KNN
        } else {
            const int e    = i - OFF_ATTR;
            const int col  = e & 15;
            const int type = ((e >> 4) >= EDGES_HALF) ? 1 : 0;
            val = edge_emb[type * 16 + col];
        }
        out[i] = val;
    }
}

// ---------------------------------------------------------------------------
extern "C" void kernel_launch(void* const* d_in, const int* in_sizes, int n_in,
                              void* d_out, int out_size) {
    const float* pos      = (const float*)d_in[0];  // [B,L,A,3] f32
    const int*   frag     = (const int*)  d_in[6];  // [B,L] i32
    const float* edge_emb = (const float*)d_in[7];  // [2,16] f32
    float* out = (float*)d_out;

    {
        dim3 grid(NTILES, Bb);
        block_dist_kernel<<<grid, 256>>>(pos);
    }
    {
        knn_fill_kernel<<<KNN_CTAS + FILL_CTAS, 256>>>(frag, edge_emb, out);
    }
    (void)in_sizes; (void)n_in; (void)out_size;
}